// round 1
// baseline (speedup 1.0000x reference)
#include <cuda_runtime.h>
#include <cuda_bf16.h>

// AGNNConv:
//   Xp = X @ W                       [N,64]
//   e_attn[e] = dot(Xp[row[e]], Xp[col[e]]) * w
//   out[i] = sum_{e: row[e]==i} e_attn[e] * Xp[col[e]]
//
// Inputs (metadata order): X [N*64 f32], weights [64*64 f32],
//   attention_w [1 f32], row [E i32, sorted], col [E i32]
// Output: out [N*64 f32]

#define D 64
#define MAX_NODES 50000
#define EPW 32            // edges per warp

// scratch for transformed features (no cudaMalloc allowed)
__device__ float2 g_Xp[MAX_NODES * (D / 2)];

// ---------------------------------------------------------------------------
// Kernel 1: Xp = X @ W, and zero out. 4 rows per 256-thread block.
// ---------------------------------------------------------------------------
__global__ void __launch_bounds__(256)
gemm_zero_kernel(const float* __restrict__ X, const float* __restrict__ W,
                 float* __restrict__ out, int n_nodes)
{
    __shared__ float Ws[D * D];     // 16 KB
    __shared__ float Xs[4][D];

    int t = threadIdx.x;
    #pragma unroll
    for (int i = t; i < D * D; i += 256) Ws[i] = W[i];

    int lr = t >> 6;        // 0..3 local row
    int d  = t & 63;        // 0..63 output dim
    int r  = blockIdx.x * 4 + lr;

    if (r < n_nodes) Xs[lr][d] = X[r * D + d];
    __syncthreads();

    if (r >= n_nodes) return;

    float acc = 0.f;
    #pragma unroll
    for (int k = 0; k < D; ++k)
        acc = fmaf(Xs[lr][k], Ws[k * D + d], acc);

    // write Xp as float2-packed array: element (r, d) lives at
    // g_Xp[r*32 + d/2].{x,y}. Write scalar via float view.
    reinterpret_cast<float*>(g_Xp)[r * D + d] = acc;
    out[r * D + d] = 0.f;
}

// ---------------------------------------------------------------------------
// Kernel 2: edge SDDMM + register-accumulated SpMM scatter.
// One warp handles EPW consecutive edges. Lane l owns dims (2l, 2l+1).
// Since row[] is sorted, accumulate in registers while the destination is
// unchanged; flush with atomicAdd on change / at chunk end.
// ---------------------------------------------------------------------------
__global__ void __launch_bounds__(256)
edge_kernel(const int* __restrict__ row, const int* __restrict__ col,
            const float* __restrict__ attn_w, float* __restrict__ out,
            int n_edges)
{
    int warp_id = (blockIdx.x * blockDim.x + threadIdx.x) >> 5;
    int lane    = threadIdx.x & 31;

    int e0 = warp_id * EPW;
    if (e0 >= n_edges) return;
    int e1 = min(e0 + EPW, n_edges);

    const float w = attn_w[0];

    int cur_r = row[e0];
    float2 xr = g_Xp[cur_r * 32 + lane];
    float2 acc = make_float2(0.f, 0.f);

    for (int e = e0; e < e1; ++e) {
        int r = row[e];
        int c = col[e];

        if (r != cur_r) {
            // flush accumulated segment
            atomicAdd(&out[cur_r * D + 2 * lane],     acc.x);
            atomicAdd(&out[cur_r * D + 2 * lane + 1], acc.y);
            acc.x = 0.f; acc.y = 0.f;
            cur_r = r;
            xr = g_Xp[r * 32 + lane];
        }

        float2 xc = g_Xp[c * 32 + lane];
        float p = xc.x * xr.x + xc.y * xr.y;

        // warp all-reduce (sum over 32 lanes -> full 64-dim dot)
        #pragma unroll
        for (int off = 16; off; off >>= 1)
            p += __shfl_xor_sync(0xFFFFFFFFu, p, off);

        float a = p * w;
        acc.x = fmaf(a, xc.x, acc.x);
        acc.y = fmaf(a, xc.y, acc.y);
    }

    atomicAdd(&out[cur_r * D + 2 * lane],     acc.x);
    atomicAdd(&out[cur_r * D + 2 * lane + 1], acc.y);
}

// ---------------------------------------------------------------------------
extern "C" void kernel_launch(void* const* d_in, const int* in_sizes, int n_in,
                              void* d_out, int out_size)
{
    const float* X  = (const float*)d_in[0];
    const float* W  = (const float*)d_in[1];
    const float* aw = (const float*)d_in[2];
    const int*   row = (const int*)d_in[3];
    const int*   col = (const int*)d_in[4];
    float* out = (float*)d_out;

    int n_nodes = in_sizes[0] / D;
    int n_edges = in_sizes[3];

    gemm_zero_kernel<<<(n_nodes + 3) / 4, 256>>>(X, W, out, n_nodes);

    int n_warps  = (n_edges + EPW - 1) / EPW;
    int n_blocks = (n_warps + 7) / 8;
    edge_kernel<<<n_blocks, 256>>>(row, col, aw, out, n_edges);
}

// round 2
// speedup vs baseline: 1.1042x; 1.1042x over previous
#include <cuda_runtime.h>
#include <cuda_bf16.h>

// AGNNConv:
//   Xp = X @ W                       [N,64]
//   e_attn[e] = dot(Xp[row[e]], Xp[col[e]]) * w
//   out[i] = sum_{e: row[e]==i} e_attn[e] * Xp[col[e]]
//
// Inputs: X [N*64 f32], weights [64*64 f32], attention_w [1 f32],
//         row [E i32, sorted], col [E i32].  Output: out [N*64 f32]

#define D 64
#define MAX_NODES 50000
#define EPW 32              // edges per warp (16 per 16-lane sub-group)
#define ROWS_PER_BLK 32

// scratch for transformed features, float4-packed: Xp[r][d] = g_Xp4[r*16 + d/4]
__device__ float4 g_Xp4[MAX_NODES * (D / 4)];

// ---------------------------------------------------------------------------
// Kernel 1: Xp = X @ W, zero out. 32 rows per 256-thread block.
// Thread (r_local = tid>>3, dg = tid&7) computes dims [8*dg, 8*dg+8) of row.
// ---------------------------------------------------------------------------
__global__ void __launch_bounds__(256)
gemm_zero_kernel(const float* __restrict__ X, const float4* __restrict__ W4,
                 float4* __restrict__ out4, int n_nodes)
{
    __shared__ float  Ws[D * D];            // 16 KB, row-major [k][d]
    __shared__ float  Xs[ROWS_PER_BLK][D + 1]; // +1 pad: stride 65 kills conflicts

    int t = threadIdx.x;
    int r0 = blockIdx.x * ROWS_PER_BLK;

    // load W (4096 floats) via float4, 4 per thread
    float4* Ws4v = reinterpret_cast<float4*>(Ws);
    #pragma unroll
    for (int i = 0; i < 4; ++i) Ws4v[t + 256 * i] = W4[t + 256 * i];

    // load X rows (2048 floats), 8 per thread, coalesced
    #pragma unroll
    for (int i = 0; i < 8; ++i) {
        int idx = t + 256 * i;
        int r = idx >> 6, k = idx & 63;
        Xs[r][k] = (r0 + r < n_nodes) ? X[(r0 + r) * D + k] : 0.f;
    }
    __syncthreads();

    int rl = t >> 3;        // 0..31
    int dg = t & 7;         // dim group: dims 8*dg .. 8*dg+7
    int r  = r0 + rl;

    float acc[8];
    #pragma unroll
    for (int i = 0; i < 8; ++i) acc[i] = 0.f;

    const float4* Wrow = reinterpret_cast<const float4*>(Ws) + dg * 2;
    #pragma unroll
    for (int k = 0; k < D; ++k) {
        float x = Xs[rl][k];
        float4 w0 = Wrow[k * 16];
        float4 w1 = Wrow[k * 16 + 1];
        acc[0] = fmaf(x, w0.x, acc[0]);
        acc[1] = fmaf(x, w0.y, acc[1]);
        acc[2] = fmaf(x, w0.z, acc[2]);
        acc[3] = fmaf(x, w0.w, acc[3]);
        acc[4] = fmaf(x, w1.x, acc[4]);
        acc[5] = fmaf(x, w1.y, acc[5]);
        acc[6] = fmaf(x, w1.z, acc[6]);
        acc[7] = fmaf(x, w1.w, acc[7]);
    }

    if (r < n_nodes) {
        float4 z = make_float4(0.f, 0.f, 0.f, 0.f);
        int base = r * 16 + dg * 2;
        g_Xp4[base]     = make_float4(acc[0], acc[1], acc[2], acc[3]);
        g_Xp4[base + 1] = make_float4(acc[4], acc[5], acc[6], acc[7]);
        out4[base]      = z;
        out4[base + 1]  = z;
    }
}

// ---------------------------------------------------------------------------
// Kernel 2: edge SDDMM + register-accumulated SpMM scatter.
// Each warp = two 16-lane groups; group `sub` handles 16 contiguous edges
// [e0 + 16*sub, ...). Lane q (0..15) owns dims [4q, 4q+4) as a float4.
// Dot reduce = 4 shfl.xor within the 16-lane group. Flush on segment change
// with one float4 atomicAdd per lane.
// ---------------------------------------------------------------------------
__global__ void __launch_bounds__(256)
edge_kernel(const int* __restrict__ row, const int* __restrict__ col,
            const float* __restrict__ attn_w, float4* __restrict__ out4,
            int n_edges)
{
    int warp_id = (blockIdx.x * blockDim.x + threadIdx.x) >> 5;
    int lane    = threadIdx.x & 31;
    int sub     = lane >> 4;          // 0 or 1
    int q       = lane & 15;          // dim-quad owner

    int e0 = warp_id * EPW + sub * (EPW / 2);
    if (e0 >= n_edges) return;
    int e1 = min(e0 + EPW / 2, n_edges);

    const unsigned gmask = 0xFFFFu << (sub * 16);
    const float w = __ldg(attn_w);

    int cur_r = row[e0];
    float4 xr = g_Xp4[cur_r * 16 + q];
    float4 acc = make_float4(0.f, 0.f, 0.f, 0.f);

    for (int e = e0; e < e1; ++e) {
        int r = row[e];
        int c = col[e];

        if (r != cur_r) {
            atomicAdd(&out4[cur_r * 16 + q], acc);
            acc = make_float4(0.f, 0.f, 0.f, 0.f);
            cur_r = r;
            xr = g_Xp4[r * 16 + q];
        }

        float4 xc = g_Xp4[c * 16 + q];
        float p = xc.x * xr.x + xc.y * xr.y + xc.z * xr.z + xc.w * xr.w;

        // reduce across the 16-lane group (xor offsets stay inside group)
        p += __shfl_xor_sync(gmask, p, 8);
        p += __shfl_xor_sync(gmask, p, 4);
        p += __shfl_xor_sync(gmask, p, 2);
        p += __shfl_xor_sync(gmask, p, 1);

        float a = p * w;
        acc.x = fmaf(a, xc.x, acc.x);
        acc.y = fmaf(a, xc.y, acc.y);
        acc.z = fmaf(a, xc.z, acc.z);
        acc.w = fmaf(a, xc.w, acc.w);
    }

    atomicAdd(&out4[cur_r * 16 + q], acc);
}

// ---------------------------------------------------------------------------
extern "C" void kernel_launch(void* const* d_in, const int* in_sizes, int n_in,
                              void* d_out, int out_size)
{
    const float* X  = (const float*)d_in[0];
    const float4* W4 = (const float4*)d_in[1];
    const float* aw = (const float*)d_in[2];
    const int*   row = (const int*)d_in[3];
    const int*   col = (const int*)d_in[4];
    float4* out4 = (float4*)d_out;

    int n_nodes = in_sizes[0] / D;
    int n_edges = in_sizes[3];

    gemm_zero_kernel<<<(n_nodes + ROWS_PER_BLK - 1) / ROWS_PER_BLK, 256>>>(
        X, W4, out4, n_nodes);

    int n_warps  = (n_edges + EPW - 1) / EPW;
    int n_blocks = (n_warps + 7) / 8;
    edge_kernel<<<n_blocks, 256>>>(row, col, aw, out4, n_edges);
}

// round 3
// speedup vs baseline: 1.8080x; 1.6375x over previous
#include <cuda_runtime.h>
#include <cuda_bf16.h>

// AGNNConv:
//   Xp = X @ W;  attn[e] = dot(Xp[row[e]], Xp[col[e]]) * w
//   out[i] = sum_{e: row[e]==i} attn[e] * Xp[col[e]]
// Inputs: X [N*64 f32], W [64*64 f32], attention_w [1 f32],
//         row [E i32 sorted], col [E i32].  Output: out [N*64 f32]

#define D 64
#define MAX_NODES 50000
#define EPW 32              // edges per warp (16 per 16-lane sub-group)
#define RPB 128             // rows per block (gemm)
#define XS_STRIDE 72        // padded row stride in floats (float4-store friendly)

__device__ float4 g_Xp4[MAX_NODES * (D / 4)];

// ---------------------------------------------------------------------------
// Kernel 1: Xp = X @ W + zero out.  256 threads, 128 rows/block.
// Thread (rg = t>>3, dg = t&7) computes rows [4rg,4rg+4) x cols [8dg,8dg+8).
// Per k: 4 broadcast LDS.32 (X) + 2 LDS.128 (W) -> 32 FFMA.
// ---------------------------------------------------------------------------
__global__ void __launch_bounds__(256)
gemm_zero_kernel(const float4* __restrict__ X4, const float4* __restrict__ W4,
                 float4* __restrict__ out4, int n_nodes)
{
    __shared__ float Ws[D * D];                 // 16 KB  [k][d]
    __shared__ float Xs[RPB * XS_STRIDE];       // 36.9 KB, row r at r*72

    int t  = threadIdx.x;
    int r0 = blockIdx.x * RPB;

    // load W: 1024 float4, 4 per thread
    float4* Ws4v = reinterpret_cast<float4*>(Ws);
    #pragma unroll
    for (int i = 0; i < 4; ++i) Ws4v[t + 256 * i] = W4[t + 256 * i];

    // load X: 128 rows x 16 float4 = 2048 float4, 8 per thread
    #pragma unroll
    for (int i = 0; i < 8; ++i) {
        int idx4 = t + 256 * i;          // float4 index within tile
        int r  = idx4 >> 4;              // 0..127
        int k4 = idx4 & 15;              // 0..15
        float4 v = (r0 + r < n_nodes) ? X4[(r0 + r) * 16 + k4]
                                      : make_float4(0.f, 0.f, 0.f, 0.f);
        *reinterpret_cast<float4*>(&Xs[r * XS_STRIDE + k4 * 4]) = v;
    }
    __syncthreads();

    int rg = t >> 3;                     // 0..31 -> rows 4rg..4rg+3
    int dg = t & 7;                      // cols 8dg..8dg+7

    float acc[4][8];
    #pragma unroll
    for (int i = 0; i < 4; ++i)
        #pragma unroll
        for (int j = 0; j < 8; ++j) acc[i][j] = 0.f;

    const float* xbase = &Xs[(rg * 4) * XS_STRIDE];
    const float4* Wq = reinterpret_cast<const float4*>(Ws) + dg * 2;

    #pragma unroll 8
    for (int k = 0; k < D; ++k) {
        float4 w0 = Wq[k * 16];
        float4 w1 = Wq[k * 16 + 1];
        #pragma unroll
        for (int i = 0; i < 4; ++i) {
            float x = xbase[i * XS_STRIDE + k];
            acc[i][0] = fmaf(x, w0.x, acc[i][0]);
            acc[i][1] = fmaf(x, w0.y, acc[i][1]);
            acc[i][2] = fmaf(x, w0.z, acc[i][2]);
            acc[i][3] = fmaf(x, w0.w, acc[i][3]);
            acc[i][4] = fmaf(x, w1.x, acc[i][4]);
            acc[i][5] = fmaf(x, w1.y, acc[i][5]);
            acc[i][6] = fmaf(x, w1.z, acc[i][6]);
            acc[i][7] = fmaf(x, w1.w, acc[i][7]);
        }
    }

    float4 z = make_float4(0.f, 0.f, 0.f, 0.f);
    #pragma unroll
    for (int i = 0; i < 4; ++i) {
        int r = r0 + rg * 4 + i;
        if (r < n_nodes) {
            int base = r * 16 + dg * 2;
            g_Xp4[base]     = make_float4(acc[i][0], acc[i][1], acc[i][2], acc[i][3]);
            g_Xp4[base + 1] = make_float4(acc[i][4], acc[i][5], acc[i][6], acc[i][7]);
            out4[base]      = z;
            out4[base + 1]  = z;
        }
    }
}

// ---------------------------------------------------------------------------
// Kernel 2: edge SDDMM + register-accumulated SpMM scatter (unchanged).
// Warp = two 16-lane groups, 16 contiguous edges each; lane q owns dims
// [4q,4q+4). Flush on sorted-segment change with one float4 atomicAdd.
// ---------------------------------------------------------------------------
__global__ void __launch_bounds__(256)
edge_kernel(const int* __restrict__ row, const int* __restrict__ col,
            const float* __restrict__ attn_w, float4* __restrict__ out4,
            int n_edges)
{
    int warp_id = (blockIdx.x * blockDim.x + threadIdx.x) >> 5;
    int lane    = threadIdx.x & 31;
    int sub     = lane >> 4;
    int q       = lane & 15;

    int e0 = warp_id * EPW + sub * (EPW / 2);
    if (e0 >= n_edges) return;
    int e1 = min(e0 + EPW / 2, n_edges);

    const unsigned gmask = 0xFFFFu << (sub * 16);
    const float w = __ldg(attn_w);

    int cur_r = row[e0];
    float4 xr = g_Xp4[cur_r * 16 + q];
    float4 acc = make_float4(0.f, 0.f, 0.f, 0.f);

    for (int e = e0; e < e1; ++e) {
        int r = row[e];
        int c = col[e];

        if (r != cur_r) {
            atomicAdd(&out4[cur_r * 16 + q], acc);
            acc = make_float4(0.f, 0.f, 0.f, 0.f);
            cur_r = r;
            xr = g_Xp4[r * 16 + q];
        }

        float4 xc = g_Xp4[c * 16 + q];
        float p = xc.x * xr.x + xc.y * xr.y + xc.z * xr.z + xc.w * xr.w;

        p += __shfl_xor_sync(gmask, p, 8);
        p += __shfl_xor_sync(gmask, p, 4);
        p += __shfl_xor_sync(gmask, p, 2);
        p += __shfl_xor_sync(gmask, p, 1);

        float a = p * w;
        acc.x = fmaf(a, xc.x, acc.x);
        acc.y = fmaf(a, xc.y, acc.y);
        acc.z = fmaf(a, xc.z, acc.z);
        acc.w = fmaf(a, xc.w, acc.w);
    }

    atomicAdd(&out4[cur_r * 16 + q], acc);
}

// ---------------------------------------------------------------------------
extern "C" void kernel_launch(void* const* d_in, const int* in_sizes, int n_in,
                              void* d_out, int out_size)
{
    const float4* X4 = (const float4*)d_in[0];
    const float4* W4 = (const float4*)d_in[1];
    const float*  aw = (const float*)d_in[2];
    const int*   row = (const int*)d_in[3];
    const int*   col = (const int*)d_in[4];
    float4* out4 = (float4*)d_out;

    int n_nodes = in_sizes[0] / D;
    int n_edges = in_sizes[3];

    gemm_zero_kernel<<<(n_nodes + RPB - 1) / RPB, 256>>>(X4, W4, out4, n_nodes);

    int n_warps  = (n_edges + EPW - 1) / EPW;
    int n_blocks = (n_warps + 7) / 8;
    edge_kernel<<<n_blocks, 256>>>(row, col, aw, out4, n_edges);
}

// round 4
// speedup vs baseline: 2.0856x; 1.1535x over previous
#include <cuda_runtime.h>
#include <cuda_bf16.h>

// AGNNConv:
//   Xp = X @ W;  attn[e] = dot(Xp[row[e]], Xp[col[e]]) * w
//   out[i] = sum_{e: row[e]==i} attn[e] * Xp[col[e]]
// Inputs: X [N*64 f32], W [64*64 f32], attention_w [1 f32],
//         row [E i32 sorted], col [E i32].  Output: out [N*64 f32]

#define D 64
#define MAX_NODES 50000
#define EPG 16              // edges per 8-lane group
#define EPW (4 * EPG)       // edges per warp (4 groups)
#define RPB 128             // rows per block (gemm)
#define XS_STRIDE 72

__device__ float4 g_Xp4[MAX_NODES * (D / 4)];

// ---------------------------------------------------------------------------
// Kernel 1: Xp = X @ W + zero out.  256 threads, 128 rows/block.
// Thread (rg=t>>3, dg=t&7): rows [4rg,4rg+4) x cols [8dg,8dg+8).
// ---------------------------------------------------------------------------
__global__ void __launch_bounds__(256)
gemm_zero_kernel(const float4* __restrict__ X4, const float4* __restrict__ W4,
                 float4* __restrict__ out4, int n_nodes)
{
    __shared__ float Ws[D * D];
    __shared__ float Xs[RPB * XS_STRIDE];

    int t  = threadIdx.x;
    int r0 = blockIdx.x * RPB;

    float4* Ws4v = reinterpret_cast<float4*>(Ws);
    #pragma unroll
    for (int i = 0; i < 4; ++i) Ws4v[t + 256 * i] = W4[t + 256 * i];

    #pragma unroll
    for (int i = 0; i < 8; ++i) {
        int idx4 = t + 256 * i;
        int r  = idx4 >> 4;
        int k4 = idx4 & 15;
        float4 v = (r0 + r < n_nodes) ? X4[(r0 + r) * 16 + k4]
                                      : make_float4(0.f, 0.f, 0.f, 0.f);
        *reinterpret_cast<float4*>(&Xs[r * XS_STRIDE + k4 * 4]) = v;
    }
    __syncthreads();

    int rg = t >> 3;
    int dg = t & 7;

    float acc[4][8];
    #pragma unroll
    for (int i = 0; i < 4; ++i)
        #pragma unroll
        for (int j = 0; j < 8; ++j) acc[i][j] = 0.f;

    const float* xbase = &Xs[(rg * 4) * XS_STRIDE];
    const float4* Wq = reinterpret_cast<const float4*>(Ws) + dg * 2;

    #pragma unroll 8
    for (int k = 0; k < D; ++k) {
        float4 w0 = Wq[k * 16];
        float4 w1 = Wq[k * 16 + 1];
        #pragma unroll
        for (int i = 0; i < 4; ++i) {
            float x = xbase[i * XS_STRIDE + k];
            acc[i][0] = fmaf(x, w0.x, acc[i][0]);
            acc[i][1] = fmaf(x, w0.y, acc[i][1]);
            acc[i][2] = fmaf(x, w0.z, acc[i][2]);
            acc[i][3] = fmaf(x, w0.w, acc[i][3]);
            acc[i][4] = fmaf(x, w1.x, acc[i][4]);
            acc[i][5] = fmaf(x, w1.y, acc[i][5]);
            acc[i][6] = fmaf(x, w1.z, acc[i][6]);
            acc[i][7] = fmaf(x, w1.w, acc[i][7]);
        }
    }

    float4 z = make_float4(0.f, 0.f, 0.f, 0.f);
    #pragma unroll
    for (int i = 0; i < 4; ++i) {
        int r = r0 + rg * 4 + i;
        if (r < n_nodes) {
            int base = r * 16 + dg * 2;
            g_Xp4[base]     = make_float4(acc[i][0], acc[i][1], acc[i][2], acc[i][3]);
            g_Xp4[base + 1] = make_float4(acc[i][4], acc[i][5], acc[i][6], acc[i][7]);
            out4[base]      = z;
            out4[base + 1]  = z;
        }
    }
}

// ---------------------------------------------------------------------------
// Kernel 2: edge SDDMM + register SpMM scatter, 8 lanes per edge.
// Warp = 4 groups of 8 lanes; group g handles EPG contiguous edges.
// Lane q (0..7) owns quads q and q+8 (dims 4q..4q+3 and 32+4q..32+4q+3),
// so each group-level LDG.128 is exactly one 128B line.
// Dot all-reduce = 3 shfl.xor (offsets 4,2,1) serving all 4 groups at once.
// Sorted rows -> register accumulate, float4 atomic flush on segment change.
// ---------------------------------------------------------------------------
__global__ void __launch_bounds__(256)
edge_kernel(const int* __restrict__ row, const int* __restrict__ col,
            const float* __restrict__ attn_w, float4* __restrict__ out4,
            int n_edges)
{
    int warp_id = (blockIdx.x * blockDim.x + threadIdx.x) >> 5;
    int lane    = threadIdx.x & 31;
    int g       = lane >> 3;       // group 0..3
    int q       = lane & 7;        // quad owner

    int wbase = warp_id * EPW;
    if (wbase >= n_edges) return;

    int e0 = wbase + g * EPG;
    bool any = e0 < n_edges;
    int e_end = any ? min(e0 + EPG, n_edges) : e0;

    const float w = __ldg(attn_w);

    int cur_r = any ? row[e0] : 0;
    float4 xr0 = g_Xp4[cur_r * 16 + q];
    float4 xr1 = g_Xp4[cur_r * 16 + 8 + q];
    float4 acc0 = make_float4(0.f, 0.f, 0.f, 0.f);
    float4 acc1 = make_float4(0.f, 0.f, 0.f, 0.f);

    #pragma unroll 4
    for (int i = 0; i < EPG; ++i) {
        int e = e0 + i;
        bool valid = any && (e < e_end);
        int ec = valid ? e : (any ? e0 : 0);

        int r = row[ec];
        int c = col[ec];

        if (valid && r != cur_r) {
            atomicAdd(&out4[cur_r * 16 + q],     acc0);
            atomicAdd(&out4[cur_r * 16 + 8 + q], acc1);
            acc0 = make_float4(0.f, 0.f, 0.f, 0.f);
            acc1 = make_float4(0.f, 0.f, 0.f, 0.f);
            cur_r = r;
            xr0 = g_Xp4[r * 16 + q];
            xr1 = g_Xp4[r * 16 + 8 + q];
        }

        float4 xc0 = g_Xp4[c * 16 + q];
        float4 xc1 = g_Xp4[c * 16 + 8 + q];

        float p = xc0.x * xr0.x + xc0.y * xr0.y + xc0.z * xr0.z + xc0.w * xr0.w
                + xc1.x * xr1.x + xc1.y * xr1.y + xc1.z * xr1.z + xc1.w * xr1.w;

        // all-reduce within each 8-lane group; one instruction serves 4 groups
        p += __shfl_xor_sync(0xFFFFFFFFu, p, 4);
        p += __shfl_xor_sync(0xFFFFFFFFu, p, 2);
        p += __shfl_xor_sync(0xFFFFFFFFu, p, 1);

        if (valid) {
            float a = p * w;
            acc0.x = fmaf(a, xc0.x, acc0.x);
            acc0.y = fmaf(a, xc0.y, acc0.y);
            acc0.z = fmaf(a, xc0.z, acc0.z);
            acc0.w = fmaf(a, xc0.w, acc0.w);
            acc1.x = fmaf(a, xc1.x, acc1.x);
            acc1.y = fmaf(a, xc1.y, acc1.y);
            acc1.z = fmaf(a, xc1.z, acc1.z);
            acc1.w = fmaf(a, xc1.w, acc1.w);
        }
    }

    if (any) {
        atomicAdd(&out4[cur_r * 16 + q],     acc0);
        atomicAdd(&out4[cur_r * 16 + 8 + q], acc1);
    }
}

// ---------------------------------------------------------------------------
extern "C" void kernel_launch(void* const* d_in, const int* in_sizes, int n_in,
                              void* d_out, int out_size)
{
    const float4* X4 = (const float4*)d_in[0];
    const float4* W4 = (const float4*)d_in[1];
    const float*  aw = (const float*)d_in[2];
    const int*   row = (const int*)d_in[3];
    const int*   col = (const int*)d_in[4];
    float4* out4 = (float4*)d_out;

    int n_nodes = in_sizes[0] / D;
    int n_edges = in_sizes[3];

    gemm_zero_kernel<<<(n_nodes + RPB - 1) / RPB, 256>>>(X4, W4, out4, n_nodes);

    int n_warps  = (n_edges + EPW - 1) / EPW;
    int n_blocks = (n_warps + 7) / 8;   // 8 warps per 256-thread block
    edge_kernel<<<n_blocks, 256>>>(row, col, aw, out4, n_edges);
}